// round 1
// baseline (speedup 1.0000x reference)
#include <cuda_runtime.h>
#include <cuda_bf16.h>
#include <math.h>

// ---------------- constants ----------------
#define T1024 1024
#define D 1024
#define H 16
#define HD 64
#define E 8
#define F 2560
#define QKVN 3072
#define FC_N (2*F)   // 5120

// ---------------- scratch (device globals; no allocation allowed) ----------------
__device__ float g_h1[T1024 * D];
__device__ float g_qkv[T1024 * QKVN];
__device__ float g_KT[H * HD * T1024];
__device__ float g_S[(long)H * T1024 * T1024];
__device__ float g_attn[T1024 * D];
__device__ float g_xres[T1024 * D];
__device__ float g_h2[T1024 * D];
__device__ float g_xg[E * T1024 * D];
__device__ float g_h12[(long)E * T1024 * FC_N];
__device__ float g_act[(long)E * T1024 * F];
__device__ int   g_cnt[E];
__device__ float g_sums[E];
__device__ int   g_tok[E * T1024];
__device__ float g_gwf[T1024];

// ---------------- small kernels ----------------
__global__ void zero_k() {
    int i = threadIdx.x;
    if (i < E) { g_cnt[i] = 0; g_sums[i] = 0.f; }
}

__global__ void layernorm_k(const float* __restrict__ x, const float* __restrict__ w,
                            const float* __restrict__ b, float* __restrict__ y) {
    int t = blockIdx.x, tid = threadIdx.x;
    const float* xr = x + (long)t * D;
    float v[4], s = 0.f, ss = 0.f;
#pragma unroll
    for (int i = 0; i < 4; i++) {
        float a = xr[tid + i * 256];
        v[i] = a; s += a; ss += a * a;
    }
    __shared__ float r1[256], r2[256];
    r1[tid] = s; r2[tid] = ss; __syncthreads();
    for (int st = 128; st > 0; st >>= 1) {
        if (tid < st) { r1[tid] += r1[tid + st]; r2[tid] += r2[tid + st]; }
        __syncthreads();
    }
    float mean = r1[0] * (1.f / D);
    float var  = r2[0] * (1.f / D) - mean * mean;
    float inv  = rsqrtf(var + 1e-5f);
#pragma unroll
    for (int i = 0; i < 4; i++) {
        int d = tid + i * 256;
        y[(long)t * D + d] = (v[i] - mean) * inv * w[d] + b[d];
    }
}

__global__ void rope_k(float* __restrict__ qkv) {
    int t = blockIdx.x, h = blockIdx.y, i = threadIdx.x; // 32 threads
    float inv = powf(10000.f, -(2.f * (float)i) / 64.f);
    float fr = (float)t * inv;
    float c = cosf(fr), s = sinf(fr);
    float* q = qkv + (long)t * QKVN + h * HD;
    float q1 = q[i], q2 = q[i + 32];
    q[i]      = q1 * c - q2 * s;
    q[i + 32] = q1 * s + q2 * c;
    float* k = q + D;
    float k1 = k[i], k2 = k[i + 32];
    k[i]      = k1 * c - k2 * s;
    k[i + 32] = k1 * s + k2 * c;
}

__global__ void ktrans_k(const float* __restrict__ qkv, float* __restrict__ kt) {
    int gid = blockIdx.x * 256 + threadIdx.x; // H*HD*T = 1M
    int k = gid & 1023;
    int d = (gid >> 10) & 63;
    int h = gid >> 16;
    kt[gid] = qkv[(long)k * QKVN + D + h * HD + d];
}

__global__ void attn_softmax_k(float* __restrict__ S, const int* __restrict__ ids) {
    int q = blockIdx.x, h = blockIdx.y, tid = threadIdx.x;
    float* row = S + ((long)h * T1024 + q) * T1024;
    int id = ids[q];
    bool glob = (id >= 2 && id < 8);
    float vals[4];
    float mx = -3.4e38f;
#pragma unroll
    for (int i = 0; i < 4; i++) {
        int k = tid + i * 256;
        bool allowed = glob || (q >= k);
        float v = allowed ? row[k] * 0.125f : -3.402823466e38f;
        vals[i] = v;
        mx = fmaxf(mx, v);
    }
    __shared__ float red[256];
    red[tid] = mx; __syncthreads();
    for (int st = 128; st > 0; st >>= 1) {
        if (tid < st) red[tid] = fmaxf(red[tid], red[tid + st]);
        __syncthreads();
    }
    float M = red[0]; __syncthreads();
    float s = 0.f;
#pragma unroll
    for (int i = 0; i < 4; i++) {
        float e = __expf(vals[i] - M);
        vals[i] = e; s += e;
    }
    red[tid] = s; __syncthreads();
    for (int st = 128; st > 0; st >>= 1) {
        if (tid < st) red[tid] += red[tid + st];
        __syncthreads();
    }
    float z = 1.f / red[0];
#pragma unroll
    for (int i = 0; i < 4; i++) row[tid + i * 256] = vals[i] * z;
}

// ---------------- generic batched SGEMM: C = A@B (+bias) (+add) ----------------
__global__ void sgemm_nn(const float* __restrict__ A, int lda, long sA,
                         const float* __restrict__ B, int ldb, long sB,
                         const float* __restrict__ bias,
                         const float* __restrict__ addsrc, int ldadd,
                         float* __restrict__ C, int ldc, long sC,
                         int M, int N, int K) {
    int z = blockIdx.z;
    A += (long)z * sA; B += (long)z * sB; C += (long)z * sC;
    int m0 = blockIdx.y * 64, n0 = blockIdx.x * 64;
    __shared__ __align__(16) float As[16][68];
    __shared__ __align__(16) float Bs[16][68];
    int tid = threadIdx.x;
    int tx = tid & 15, ty = tid >> 4;
    float acc[4][4] = {};
    for (int k0 = 0; k0 < K; k0 += 16) {
#pragma unroll
        for (int i = 0; i < 4; i++) {
            int lin = tid + i * 256;
            int kk = lin & 15, m = lin >> 4;
            As[kk][m] = A[(long)(m0 + m) * lda + k0 + kk];
        }
#pragma unroll
        for (int i = 0; i < 4; i++) {
            int lin = tid + i * 256;
            int n = lin & 63, kk = lin >> 6;
            Bs[kk][n] = B[(long)(k0 + kk) * ldb + n0 + n];
        }
        __syncthreads();
#pragma unroll
        for (int kk = 0; kk < 16; kk++) {
            float4 a = *(const float4*)&As[kk][ty * 4];
            float4 b = *(const float4*)&Bs[kk][tx * 4];
            float av[4] = {a.x, a.y, a.z, a.w};
            float bv[4] = {b.x, b.y, b.z, b.w};
#pragma unroll
            for (int i = 0; i < 4; i++)
#pragma unroll
                for (int j = 0; j < 4; j++) acc[i][j] += av[i] * bv[j];
        }
        __syncthreads();
    }
#pragma unroll
    for (int i = 0; i < 4; i++) {
        int m = m0 + ty * 4 + i;
        if (m >= M) continue;
#pragma unroll
        for (int j = 0; j < 4; j++) {
            int n = n0 + tx * 4 + j;
            if (n >= N) continue;
            float v = acc[i][j];
            if (bias)   v += bias[n];
            if (addsrc) v += addsrc[(long)m * ldadd + n];
            C[(long)m * ldc + n] = v;
        }
    }
}

// ---------------- gate + routing + gather ----------------
__global__ void gate_route_k(const float* __restrict__ h2, const float* __restrict__ gw_mat,
                             const float* __restrict__ gb) {
    int t = blockIdx.x, tid = threadIdx.x;
    const float* xr = h2 + (long)t * D;
    float p[E];
#pragma unroll
    for (int e = 0; e < E; e++) p[e] = 0.f;
    for (int d = tid; d < D; d += 256) {
        float xv = xr[d];
#pragma unroll
        for (int e = 0; e < E; e++) p[e] += xv * gw_mat[d * E + e];
    }
    __shared__ float red[256];
    __shared__ float logits[E];
    for (int e = 0; e < E; e++) {
        red[tid] = p[e]; __syncthreads();
        for (int st = 128; st > 0; st >>= 1) {
            if (tid < st) red[tid] += red[tid + st];
            __syncthreads();
        }
        if (tid == 0) logits[e] = red[0] + gb[e];
        __syncthreads();
    }
    __shared__ int sh_slot, sh_e;
    if (tid == 0) {
        float mx = -3.4e38f;
        for (int e = 0; e < E; e++) mx = fmaxf(mx, logits[e]);
        float Z = 0.f, pr[E];
        for (int e = 0; e < E; e++) { pr[e] = expf(logits[e] - mx); Z += pr[e]; }
        float best = -1.f; int bi = 0;
        for (int e = 0; e < E; e++) {
            float v = pr[e] / Z;
            if (v > best) { best = v; bi = e; }
        }
        int slot = atomicAdd(&g_cnt[bi], 1);
        atomicAdd(&g_sums[bi], best);
        g_tok[bi * T1024 + slot] = t;
        g_gwf[t] = best;
        sh_slot = slot; sh_e = bi;
    }
    __syncthreads();
    float* dst = g_xg + ((long)sh_e * T1024 + sh_slot) * D;
    for (int d = tid; d < D; d += 256) dst[d] = xr[d];
}

// ---------------- expert fc GEMM (guarded) ----------------
__global__ void moe_fc_k(const float* __restrict__ fcw, const float* __restrict__ fcb) {
    int e = blockIdx.z;
    int M = g_cnt[e];
    int m0 = blockIdx.y * 64;
    if (m0 >= M) return;
    int n0 = blockIdx.x * 64;
    const float* A = g_xg + (long)e * T1024 * D;
    const float* B = fcw + (long)e * D * FC_N;
    const float* bias = fcb + (long)e * FC_N;
    __shared__ __align__(16) float As[16][68];
    __shared__ __align__(16) float Bs[16][68];
    int tid = threadIdx.x, tx = tid & 15, ty = tid >> 4;
    float acc[4][4] = {};
    for (int k0 = 0; k0 < D; k0 += 16) {
#pragma unroll
        for (int i = 0; i < 4; i++) {
            int lin = tid + i * 256;
            int kk = lin & 15, m = lin >> 4;
            As[kk][m] = A[(long)(m0 + m) * D + k0 + kk];
        }
#pragma unroll
        for (int i = 0; i < 4; i++) {
            int lin = tid + i * 256;
            int n = lin & 63, kk = lin >> 6;
            Bs[kk][n] = B[(long)(k0 + kk) * FC_N + n0 + n];
        }
        __syncthreads();
#pragma unroll
        for (int kk = 0; kk < 16; kk++) {
            float4 a = *(const float4*)&As[kk][ty * 4];
            float4 b = *(const float4*)&Bs[kk][tx * 4];
            float av[4] = {a.x, a.y, a.z, a.w};
            float bv[4] = {b.x, b.y, b.z, b.w};
#pragma unroll
            for (int i = 0; i < 4; i++)
#pragma unroll
                for (int j = 0; j < 4; j++) acc[i][j] += av[i] * bv[j];
        }
        __syncthreads();
    }
#pragma unroll
    for (int i = 0; i < 4; i++) {
        int m = m0 + ty * 4 + i;
        if (m >= M) continue;
#pragma unroll
        for (int j = 0; j < 4; j++) {
            int n = n0 + tx * 4 + j;
            g_h12[((long)e * T1024 + m) * FC_N + n] = acc[i][j] + bias[n];
        }
    }
}

// ---------------- GLU activation (exact gelu) ----------------
__global__ void moe_act_k() {
    int e = blockIdx.z;
    int m = blockIdx.y;
    if (m >= g_cnt[e]) return;
    int f = blockIdx.x * 256 + threadIdx.x; // F = 2560, grid.x = 10
    const float* row = g_h12 + ((long)e * T1024 + m) * FC_N;
    float x1 = row[f], x2 = row[F + f];
    float g = 0.5f * x2 * (1.f + erff(x2 * 0.70710678118654752f));
    g_act[((long)e * T1024 + m) * F + f] = x1 * g;
}

// ---------------- expert out GEMM with scatter epilogue (writes FINAL output) ----------------
__global__ void moe_out_k(const float* __restrict__ ow, const float* __restrict__ ob,
                          float* __restrict__ out) {
    int e = blockIdx.z;
    int M = g_cnt[e];
    int m0 = blockIdx.y * 64;
    if (m0 >= M) return;
    int n0 = blockIdx.x * 64;
    const float* A = g_act + (long)e * T1024 * F;
    const float* B = ow + (long)e * F * D;
    const float* bias = ob + (long)e * D;
    __shared__ __align__(16) float As[16][68];
    __shared__ __align__(16) float Bs[16][68];
    int tid = threadIdx.x, tx = tid & 15, ty = tid >> 4;
    float acc[4][4] = {};
    for (int k0 = 0; k0 < F; k0 += 16) {
#pragma unroll
        for (int i = 0; i < 4; i++) {
            int lin = tid + i * 256;
            int kk = lin & 15, m = lin >> 4;
            As[kk][m] = A[(long)(m0 + m) * F + k0 + kk];
        }
#pragma unroll
        for (int i = 0; i < 4; i++) {
            int lin = tid + i * 256;
            int n = lin & 63, kk = lin >> 6;
            Bs[kk][n] = B[(long)(k0 + kk) * D + n0 + n];
        }
        __syncthreads();
#pragma unroll
        for (int kk = 0; kk < 16; kk++) {
            float4 a = *(const float4*)&As[kk][ty * 4];
            float4 b = *(const float4*)&Bs[kk][tx * 4];
            float av[4] = {a.x, a.y, a.z, a.w};
            float bv[4] = {b.x, b.y, b.z, b.w};
#pragma unroll
            for (int i = 0; i < 4; i++)
#pragma unroll
                for (int j = 0; j < 4; j++) acc[i][j] += av[i] * bv[j];
        }
        __syncthreads();
    }
#pragma unroll
    for (int i = 0; i < 4; i++) {
        int m = m0 + ty * 4 + i;
        if (m >= M) continue;
        int t = g_tok[e * T1024 + m];
        float g = g_gwf[t];
#pragma unroll
        for (int j = 0; j < 4; j++) {
            int n = n0 + tx * 4 + j;
            out[(long)t * D + n] = g_xres[(long)t * D + n] + (acc[i][j] + bias[n]) * g;
        }
    }
}

__global__ void moe_loss_k(float* __restrict__ out_loss) {
    if (threadIdx.x == 0) {
        float l = 0.f;
        for (int e = 0; e < E; e++) {
            float u = g_sums[e] / ((float)g_cnt[e] + 1e-8f);
            float d = u - 1.f / (float)E;
            l += d * d;
        }
        out_loss[0] = l;
    }
}

// ---------------- host ----------------
static float* sym_addr(const void* sym) {
    void* p = nullptr;
    cudaGetSymbolAddress(&p, sym);
    return (float*)p;
}

extern "C" void kernel_launch(void* const* d_in, const int* in_sizes, int n_in,
                              void* d_out, int out_size) {
    const float* x      = (const float*)d_in[0];
    const int*   ids    = (const int*)d_in[1];
    const float* ln1w   = (const float*)d_in[2];
    const float* ln1b   = (const float*)d_in[3];
    const float* qkvw   = (const float*)d_in[4];
    const float* qkvb   = (const float*)d_in[5];
    const float* aow    = (const float*)d_in[6];
    const float* aob    = (const float*)d_in[7];
    const float* ln2w   = (const float*)d_in[8];
    const float* ln2b   = (const float*)d_in[9];
    const float* gatew  = (const float*)d_in[10];
    const float* gateb  = (const float*)d_in[11];
    const float* fcw    = (const float*)d_in[12];
    const float* fcb    = (const float*)d_in[13];
    const float* eow    = (const float*)d_in[14];
    const float* eob    = (const float*)d_in[15];
    float* out = (float*)d_out;

    float* p_h1   = sym_addr(g_h1);
    float* p_qkv  = sym_addr(g_qkv);
    float* p_KT   = sym_addr(g_KT);
    float* p_S    = sym_addr(g_S);
    float* p_attn = sym_addr(g_attn);
    float* p_xres = sym_addr(g_xres);
    float* p_h2   = sym_addr(g_h2);

    zero_k<<<1, 32>>>();
    layernorm_k<<<T1024, 256>>>(x, ln1w, ln1b, p_h1);

    // qkv = h1 @ qkv_w + qkv_b   [1024,1024]x[1024,3072]
    sgemm_nn<<<dim3(QKVN / 64, T1024 / 64, 1), 256>>>(
        p_h1, D, 0, qkvw, QKVN, 0, qkvb, nullptr, 0,
        p_qkv, QKVN, 0, T1024, QKVN, D);

    rope_k<<<dim3(T1024, H), 32>>>(p_qkv);
    ktrans_k<<<(H * HD * T1024) / 256, 256>>>(p_qkv, p_KT);

    // S[h] = Q[h] @ K[h]^T   (per head: [1024,64]x[64,1024])
    sgemm_nn<<<dim3(16, 16, H), 256>>>(
        p_qkv, QKVN, 64, p_KT, T1024, (long)HD * T1024, nullptr, nullptr, 0,
        p_S, T1024, (long)T1024 * T1024, T1024, T1024, HD);

    attn_softmax_k<<<dim3(T1024, H), 256>>>(p_S, ids);

    // attn[h] = P[h] @ V[h]   ([1024,1024]x[1024,64]) -> concat layout
    sgemm_nn<<<dim3(1, 16, H), 256>>>(
        p_S, T1024, (long)T1024 * T1024, p_qkv + 2 * D, QKVN, 64, nullptr, nullptr, 0,
        p_attn, D, 64, T1024, HD, T1024);

    // xres = x + attn @ Wo + bo
    sgemm_nn<<<dim3(16, 16, 1), 256>>>(
        p_attn, D, 0, aow, D, 0, aob, x, D,
        p_xres, D, 0, T1024, D, D);

    layernorm_k<<<T1024, 256>>>(p_xres, ln2w, ln2b, p_h2);
    gate_route_k<<<T1024, 256>>>(p_h2, gatew, gateb);

    moe_fc_k<<<dim3(FC_N / 64, T1024 / 64, E), 256>>>(fcw, fcb);
    moe_act_k<<<dim3(F / 256, T1024, E), 256>>>();
    moe_out_k<<<dim3(D / 64, T1024 / 64, E), 256>>>(eow, eob, out);

    if (out_size > T1024 * D)
        moe_loss_k<<<1, 32>>>(out + (long)T1024 * D);
}